// round 2
// baseline (speedup 1.0000x reference)
#include <cuda_runtime.h>
#include <math.h>

#define IN_DIM 1024
#define ED 256
#define NE 512
#define BK 16

typedef unsigned long long u64;

// normalized centers, transposed to [k][e] = [256][512]
__device__ float g_cnT[ED * NE];
// projection scratch: [ntok][256]
__device__ float g_P[131072 * ED];

static __device__ __forceinline__ u64 pack2(float lo, float hi) {
    u64 r; asm("mov.b64 %0, {%1, %2};" : "=l"(r) : "f"(lo), "f"(hi)); return r;
}
static __device__ __forceinline__ void unpack2(u64 v, float& lo, float& hi) {
    asm("mov.b64 {%0, %1}, %2;" : "=f"(lo), "=f"(hi) : "l"(v));
}
static __device__ __forceinline__ void ffma2(u64& d, u64 a, u64 b) {
    asm("fma.rn.f32x2 %0, %1, %2, %0;" : "+l"(d) : "l"(a), "l"(b));
}

static __device__ __forceinline__ void upd(float v, int i,
                                           float& v1, int& i1, float& v2, int& i2) {
    if (v > v1 || (v == v1 && i < i1)) { v2 = v1; i2 = i1; v1 = v; i1 = i; }
    else if (v > v2 || (v == v2 && i < i2)) { v2 = v; i2 = i; }
}

__global__ void cnorm_kernel(const float* __restrict__ centers) {
    __shared__ float ws[8];
    int e = blockIdx.x, t = threadIdx.x;
    float v = centers[e * ED + t];
    float s = v * v;
    #pragma unroll
    for (int o = 16; o; o >>= 1) s += __shfl_xor_sync(0xffffffffu, s, o);
    if ((t & 31) == 0) ws[t >> 5] = s;
    __syncthreads();
    float tot = 0.f;
    #pragma unroll
    for (int i = 0; i < 8; ++i) tot += ws[i];
    float norm = fmaxf(sqrtf(tot), 1e-12f);
    g_cnT[t * NE + e] = v / norm;
}

// ---------------- Kernel A: P = x @ W^T + b ----------------
// block tile 64(m) x 128(n), BK=16, 256 threads, per-thread 8m x 4n.
#define XA_PITCH 66
#define WA_PITCH 132

__global__ __launch_bounds__(256, 3)
void sgemm1_kernel(const float* __restrict__ x, const float* __restrict__ W,
                   const float* __restrict__ bias) {
    __shared__ float xT[2][BK * XA_PITCH];
    __shared__ float wT[2][BK * WA_PITCH];

    const int tid = threadIdx.x;
    const int t0 = blockIdx.x * 64;
    const int bn0 = blockIdx.y * 128;

    // load assignment
    const int xr = tid >> 2, xk = (tid & 3) * 4;     // x: row, k-quad
    const int wn = tid >> 1, wk = (tid & 1) * 8;     // W: n-row, k-oct

    const float* xp = x + (size_t)(t0 + xr) * IN_DIM + xk;
    const float* wp = W + (size_t)(bn0 + wn) * IN_DIM + wk;

    float4 xs = *(const float4*)xp;
    float4 w0 = *(const float4*)wp;
    float4 w1 = *(const float4*)(wp + 4);

    const int mb = (tid >> 5) * 8;       // warp owns 8 rows (broadcast a)
    const int nA = (tid & 31) * 4;       // lane owns 4 cols

    u64 acc[4][4];
    #pragma unroll
    for (int p = 0; p < 4; ++p)
        #pragma unroll
        for (int j = 0; j < 4; ++j) acc[p][j] = 0ull;

    for (int kt = 0; kt < IN_DIM / BK; ++kt) {
        float* xb = xT[kt & 1];
        float* wb = wT[kt & 1];
        xb[(xk + 0) * XA_PITCH + xr] = xs.x;
        xb[(xk + 1) * XA_PITCH + xr] = xs.y;
        xb[(xk + 2) * XA_PITCH + xr] = xs.z;
        xb[(xk + 3) * XA_PITCH + xr] = xs.w;
        wb[(wk + 0) * WA_PITCH + wn] = w0.x;
        wb[(wk + 1) * WA_PITCH + wn] = w0.y;
        wb[(wk + 2) * WA_PITCH + wn] = w0.z;
        wb[(wk + 3) * WA_PITCH + wn] = w0.w;
        wb[(wk + 4) * WA_PITCH + wn] = w1.x;
        wb[(wk + 5) * WA_PITCH + wn] = w1.y;
        wb[(wk + 6) * WA_PITCH + wn] = w1.z;
        wb[(wk + 7) * WA_PITCH + wn] = w1.w;
        __syncthreads();
        if (kt + 1 < IN_DIM / BK) {
            xs = *(const float4*)(xp + (kt + 1) * BK);
            w0 = *(const float4*)(wp + (kt + 1) * BK);
            w1 = *(const float4*)(wp + (kt + 1) * BK + 4);
        }
        #pragma unroll
        for (int k = 0; k < BK; ++k) {
            u64 a0 = *(const u64*)(xb + k * XA_PITCH + mb + 0);
            u64 a1 = *(const u64*)(xb + k * XA_PITCH + mb + 2);
            u64 a2 = *(const u64*)(xb + k * XA_PITCH + mb + 4);
            u64 a3 = *(const u64*)(xb + k * XA_PITCH + mb + 6);
            float4 b = *(const float4*)(wb + k * WA_PITCH + nA);
            u64 b0 = pack2(b.x, b.x), b1 = pack2(b.y, b.y);
            u64 b2 = pack2(b.z, b.z), b3 = pack2(b.w, b.w);
            ffma2(acc[0][0], a0, b0); ffma2(acc[0][1], a0, b1);
            ffma2(acc[0][2], a0, b2); ffma2(acc[0][3], a0, b3);
            ffma2(acc[1][0], a1, b0); ffma2(acc[1][1], a1, b1);
            ffma2(acc[1][2], a1, b2); ffma2(acc[1][3], a1, b3);
            ffma2(acc[2][0], a2, b0); ffma2(acc[2][1], a2, b1);
            ffma2(acc[2][2], a2, b2); ffma2(acc[2][3], a2, b3);
            ffma2(acc[3][0], a3, b0); ffma2(acc[3][1], a3, b1);
            ffma2(acc[3][2], a3, b2); ffma2(acc[3][3], a3, b3);
        }
    }

    float bj[4];
    #pragma unroll
    for (int j = 0; j < 4; ++j) bj[j] = bias[bn0 + nA + j];

    #pragma unroll
    for (int p = 0; p < 4; ++p) {
        float lo[4], hi[4];
        #pragma unroll
        for (int j = 0; j < 4; ++j) {
            float l, h; unpack2(acc[p][j], l, h);
            lo[j] = l + bj[j]; hi[j] = h + bj[j];
        }
        size_t r0 = (size_t)(t0 + mb + 2 * p) * ED + bn0 + nA;
        *(float4*)(g_P + r0)      = make_float4(lo[0], lo[1], lo[2], lo[3]);
        *(float4*)(g_P + r0 + ED) = make_float4(hi[0], hi[1], hi[2], hi[3]);
    }
}

// ---------------- Kernel B: sims + top-2 + softmax ----------------
// block: 64 tokens, all 512 experts, K=256. 256 threads.
#define PS_PITCH 260
#define CT_PITCH 260

__global__ __launch_bounds__(256, 2)
void router2_kernel(float* __restrict__ out, int ntok) {
    extern __shared__ float smem[];
    float* Ps = smem;                        // [64][PS_PITCH]
    float* ct = smem + 64 * PS_PITCH;        // [2][BK][CT_PITCH]

    const int tid = threadIdx.x;
    const int t0 = blockIdx.x * 64;
    const int tm = tid >> 5, lane = tid & 31;
    const int mb = tm * 8;
    const int nA = lane * 4, nB = 128 + lane * 4;

    // load P tile (coalesced), row-major into smem
    #pragma unroll
    for (int c = 0; c < 16; ++c) {
        int flat = tid + c * 256;            // float4 index within 64x256
        int row = flat >> 6, colq = flat & 63;
        float4 v = *(const float4*)(g_P + (size_t)(t0 + row) * ED + colq * 4);
        *(float4*)(Ps + row * PS_PITCH + colq * 4) = v;
    }
    __syncthreads();

    // per-row sumsq: warp tm owns rows mb..mb+8
    float sq[8];
    #pragma unroll
    for (int r = 0; r < 8; ++r) {
        float s = 0.f;
        #pragma unroll
        for (int j = 0; j < 8; ++j) {
            float v = Ps[(mb + r) * PS_PITCH + lane + 32 * j];
            s += v * v;
        }
        #pragma unroll
        for (int o = 16; o; o >>= 1) s += __shfl_xor_sync(0xffffffffu, s, o);
        sq[r] = s;
    }

    float v1[8], v2[8]; int i1[8], i2[8];
    #pragma unroll
    for (int r = 0; r < 8; ++r) { v1[r] = -INFINITY; v2[r] = -INFINITY; i1[r] = 0; i2[r] = 0; }

    const int ckr = tid >> 4;                // k row within tile (0..15)
    const int e4 = (tid & 15) * 4;           // col base

    u64 acc[4][8];

    for (int ch = 0; ch < 2; ++ch) {
        #pragma unroll
        for (int p = 0; p < 4; ++p)
            #pragma unroll
            for (int j = 0; j < 8; ++j) acc[p][j] = 0ull;

        const float* cp = g_cnT + (size_t)ckr * NE + ch * 256 + e4;
        float4 cs0 = *(const float4*)(cp + 0);
        float4 cs1 = *(const float4*)(cp + 64);
        float4 cs2 = *(const float4*)(cp + 128);
        float4 cs3 = *(const float4*)(cp + 192);

        for (int kt = 0; kt < ED / BK; ++kt) {
            float* cb = ct + (kt & 1) * (BK * CT_PITCH);
            *(float4*)(cb + ckr * CT_PITCH + e4 + 0)   = cs0;
            *(float4*)(cb + ckr * CT_PITCH + e4 + 64)  = cs1;
            *(float4*)(cb + ckr * CT_PITCH + e4 + 128) = cs2;
            *(float4*)(cb + ckr * CT_PITCH + e4 + 192) = cs3;
            __syncthreads();
            if (kt + 1 < ED / BK) {
                const float* cn = cp + (size_t)(kt + 1) * BK * NE;
                cs0 = *(const float4*)(cn + 0);
                cs1 = *(const float4*)(cn + 64);
                cs2 = *(const float4*)(cn + 128);
                cs3 = *(const float4*)(cn + 192);
            }
            #pragma unroll
            for (int k = 0; k < BK; ++k) {
                u64 a[4];
                #pragma unroll
                for (int p = 0; p < 4; ++p) {
                    float l = Ps[(mb + 2 * p) * PS_PITCH + kt * BK + k];
                    float h = Ps[(mb + 2 * p + 1) * PS_PITCH + kt * BK + k];
                    a[p] = pack2(l, h);
                }
                float4 b0 = *(const float4*)(cb + k * CT_PITCH + nA);
                float4 b1 = *(const float4*)(cb + k * CT_PITCH + nB);
                u64 bb[8];
                bb[0] = pack2(b0.x, b0.x); bb[1] = pack2(b0.y, b0.y);
                bb[2] = pack2(b0.z, b0.z); bb[3] = pack2(b0.w, b0.w);
                bb[4] = pack2(b1.x, b1.x); bb[5] = pack2(b1.y, b1.y);
                bb[6] = pack2(b1.z, b1.z); bb[7] = pack2(b1.w, b1.w);
                #pragma unroll
                for (int j = 0; j < 8; ++j) {
                    ffma2(acc[0][j], a[0], bb[j]);
                    ffma2(acc[1][j], a[1], bb[j]);
                    ffma2(acc[2][j], a[2], bb[j]);
                    ffma2(acc[3][j], a[3], bb[j]);
                }
            }
        }
        // fold this chunk of 256 experts into the running per-lane top-2
        #pragma unroll
        for (int p = 0; p < 4; ++p) {
            #pragma unroll
            for (int j = 0; j < 8; ++j) {
                float l, h; unpack2(acc[p][j], l, h);
                int gi = ch * 256 + ((j < 4) ? (nA + j) : (nB + j - 4));
                upd(l, gi, v1[2 * p],     i1[2 * p],     v2[2 * p],     i2[2 * p]);
                upd(h, gi, v1[2 * p + 1], i1[2 * p + 1], v2[2 * p + 1], i2[2 * p + 1]);
            }
        }
    }

    // warp butterfly merge of top-2 across the 32 lanes (full 512 experts)
    #pragma unroll
    for (int r = 0; r < 8; ++r) {
        #pragma unroll
        for (int o = 16; o; o >>= 1) {
            float o1 = __shfl_xor_sync(0xffffffffu, v1[r], o);
            int  oi1 = __shfl_xor_sync(0xffffffffu, i1[r], o);
            float o2 = __shfl_xor_sync(0xffffffffu, v2[r], o);
            int  oi2 = __shfl_xor_sync(0xffffffffu, i2[r], o);
            upd(o1, oi1, v1[r], i1[r], v2[r], i2[r]);
            upd(o2, oi2, v1[r], i1[r], v2[r], i2[r]);
        }
    }

    if (lane == 0) {
        float* oi = out + 2 * (size_t)ntok;
        #pragma unroll
        for (int r = 0; r < 8; ++r) {
            int token = t0 + mb + r;
            float inv = 1.f / fmaxf(sqrtf(sq[r]), 1e-12f);
            float V1 = v1[r] * inv, V2 = v2[r] * inv;
            float e2 = expf(V2 - V1);
            float den = 1.f + e2;
            out[2 * token]     = 1.f / den;
            out[2 * token + 1] = e2 / den;
            oi[2 * token]      = (float)i1[r];
            oi[2 * token + 1]  = (float)i2[r];
        }
    }
}

extern "C" void kernel_launch(void* const* d_in, const int* in_sizes, int n_in,
                              void* d_out, int out_size) {
    const float* x = (const float*)d_in[0];
    const float* W = (const float*)d_in[1];
    const float* b = (const float*)d_in[2];
    const float* c = (const float*)d_in[3];
    int ntok = in_sizes[0] / IN_DIM;   // 131072

    cnorm_kernel<<<NE, ED>>>(c);

    dim3 gridA(ntok / 64, 2);
    sgemm1_kernel<<<gridA, 256>>>(x, W, b);

    int smemB = (64 * PS_PITCH + 2 * BK * CT_PITCH) * (int)sizeof(float);
    cudaFuncSetAttribute(router2_kernel, cudaFuncAttributeMaxDynamicSharedMemorySize, smemB);
    router2_kernel<<<ntok / 64, 256, smemB>>>((float*)d_out, ntok);
}

// round 3
// speedup vs baseline: 2.0822x; 2.0822x over previous
#include <cuda_runtime.h>
#include <math.h>
#include <stdint.h>

#define IN_DIM 1024
#define ED 256
#define NE 512
#define BK 16
#define NTOK_MAX 131072
#define TT 32
#define PSTP 34
#define XDP 132

typedef unsigned long long u64;

__device__ __align__(16) float g_WT[IN_DIM * ED];     // W transposed [k][n]
__device__ __align__(16) float g_cnT[ED * NE];        // normalized centers [k][e]
__device__ __align__(16) float g_P[(size_t)NTOK_MAX * ED];
__device__ float g_sq[NTOK_MAX];

static __device__ __forceinline__ u64 pack2(float lo, float hi) {
    u64 r; asm("mov.b64 %0, {%1, %2};" : "=l"(r) : "f"(lo), "f"(hi)); return r;
}
static __device__ __forceinline__ void unpack2(u64 v, float& lo, float& hi) {
    asm("mov.b64 {%0, %1}, %2;" : "=f"(lo), "=f"(hi) : "l"(v));
}
static __device__ __forceinline__ void ffma2(u64& d, u64 a, u64 b) {
    asm("fma.rn.f32x2 %0, %1, %2, %0;" : "+l"(d) : "l"(a), "l"(b));
}
static __device__ __forceinline__ void fadd2(u64& d, u64 a) {
    asm("add.rn.f32x2 %0, %0, %1;" : "+l"(d) : "l"(a));
}
static __device__ __forceinline__ void cpa16(uint32_t dst, const float* src) {
    asm volatile("cp.async.cg.shared.global [%0], [%1], 16;" :: "r"(dst), "l"(src));
}
#define CP_COMMIT asm volatile("cp.async.commit_group;")
#define CP_WAIT0  asm volatile("cp.async.wait_group 0;")

static __device__ __forceinline__ void upd(float v, int i,
                                           float& v1, int& i1, float& v2, int& i2) {
    if (v > v1 || (v == v1 && i < i1)) { v2 = v1; i2 = i1; v1 = v; i1 = i; }
    else if (v > v2 || (v == v2 && i < i2)) { v2 = v; i2 = i; }
}

// ---------------- prep: normalize centers -> g_cnT [k][e] ----------------
__global__ void cnorm_kernel(const float* __restrict__ centers) {
    __shared__ float ws[8];
    int e = blockIdx.x, t = threadIdx.x;
    float v = centers[e * ED + t];
    float s = v * v;
    #pragma unroll
    for (int o = 16; o; o >>= 1) s += __shfl_xor_sync(0xffffffffu, s, o);
    if ((t & 31) == 0) ws[t >> 5] = s;
    __syncthreads();
    float tot = 0.f;
    #pragma unroll
    for (int i = 0; i < 8; ++i) tot += ws[i];
    float norm = fmaxf(sqrtf(tot), 1e-12f);
    g_cnT[t * NE + e] = v / norm;
}

// ---------------- prep: transpose W [n][k] -> g_WT [k][n] ----------------
__global__ void prep_wt_kernel(const float* __restrict__ W) {
    __shared__ float t[32][33];
    int bx = blockIdx.x * 32;   // k block
    int by = blockIdx.y * 32;   // n block
    int x = threadIdx.x, y = threadIdx.y;
    #pragma unroll
    for (int j = 0; j < 32; j += 8)
        t[y + j][x] = W[(size_t)(by + y + j) * IN_DIM + bx + x];
    __syncthreads();
    #pragma unroll
    for (int j = 0; j < 32; j += 8)
        g_WT[(size_t)(bx + y + j) * ED + by + x] = t[x][y + j];
}

// ---------------- K1: P = x @ W^T + b  (n-pair packed accs) ----------------
__global__ __launch_bounds__(256, 2)
void k1_kernel(const float* __restrict__ x, const float* __restrict__ bias) {
    extern __shared__ __align__(16) float sm1[];
    float* xd = sm1;                       // [2][BK][XDP]  duplicated x, k-major
    float* wS = sm1 + 2 * BK * XDP;        // [2][BK][ED]   W tile, k-major

    const int tid = threadIdx.x;
    const int w = tid >> 5, lane = tid & 31;
    const int t0 = blockIdx.x * 64;
    const int mb = w * 8;
    const int nA = lane * 4, nB = 128 + lane * 4;

    const int xr = tid >> 2, xk = (tid & 3) * 4;
    const float* xp = x + (size_t)(t0 + xr) * IN_DIM + xk;
    const int wr = tid >> 6, wc = (tid & 63) * 4;

    uint32_t wS_u32 = (uint32_t)__cvta_generic_to_shared(wS);

    u64 acc[8][4];
    #pragma unroll
    for (int m = 0; m < 8; ++m)
        #pragma unroll
        for (int p = 0; p < 4; ++p) acc[m][p] = 0ull;

    // prologue (kt = 0)
    float4 xs = *(const float4*)xp;
    #pragma unroll
    for (int j = 0; j < 4; ++j)
        cpa16(wS_u32 + (uint32_t)(((wr + 4 * j) * ED + wc) * 4),
              g_WT + (size_t)(wr + 4 * j) * ED + wc);
    CP_COMMIT;
    #pragma unroll
    for (int i = 0; i < 4; ++i) {
        float v = (i == 0) ? xs.x : (i == 1) ? xs.y : (i == 2) ? xs.z : xs.w;
        *(float2*)(xd + (xk + i) * XDP + 2 * xr) = make_float2(v, v);
    }
    CP_WAIT0;
    __syncthreads();

    for (int kt = 0; kt < IN_DIM / BK; ++kt) {
        const int buf = kt & 1;
        const float* xb = xd + buf * (BK * XDP);
        const float* wb = wS + buf * (BK * ED);
        if (kt + 1 < IN_DIM / BK) {
            xs = *(const float4*)(xp + (kt + 1) * BK);
            const float* wsrc = g_WT + (size_t)((kt + 1) * BK) * ED;
            uint32_t wdst = wS_u32 + (uint32_t)((buf ^ 1) * (BK * ED * 4));
            #pragma unroll
            for (int j = 0; j < 4; ++j)
                cpa16(wdst + (uint32_t)(((wr + 4 * j) * ED + wc) * 4),
                      wsrc + (size_t)(wr + 4 * j) * ED + wc);
            CP_COMMIT;
        }
        #pragma unroll
        for (int k = 0; k < BK; ++k) {
            ulonglong2 qa0 = *(const ulonglong2*)(xb + k * XDP + 2 * mb + 0);
            ulonglong2 qa1 = *(const ulonglong2*)(xb + k * XDP + 2 * mb + 4);
            ulonglong2 qa2 = *(const ulonglong2*)(xb + k * XDP + 2 * mb + 8);
            ulonglong2 qa3 = *(const ulonglong2*)(xb + k * XDP + 2 * mb + 12);
            ulonglong2 qb0 = *(const ulonglong2*)(wb + k * ED + nA);
            ulonglong2 qb1 = *(const ulonglong2*)(wb + k * ED + nB);
            u64 B0 = qb0.x, B1 = qb0.y, B2 = qb1.x, B3 = qb1.y;
            ffma2(acc[0][0], qa0.x, B0); ffma2(acc[0][1], qa0.x, B1);
            ffma2(acc[0][2], qa0.x, B2); ffma2(acc[0][3], qa0.x, B3);
            ffma2(acc[1][0], qa0.y, B0); ffma2(acc[1][1], qa0.y, B1);
            ffma2(acc[1][2], qa0.y, B2); ffma2(acc[1][3], qa0.y, B3);
            ffma2(acc[2][0], qa1.x, B0); ffma2(acc[2][1], qa1.x, B1);
            ffma2(acc[2][2], qa1.x, B2); ffma2(acc[2][3], qa1.x, B3);
            ffma2(acc[3][0], qa1.y, B0); ffma2(acc[3][1], qa1.y, B1);
            ffma2(acc[3][2], qa1.y, B2); ffma2(acc[3][3], qa1.y, B3);
            ffma2(acc[4][0], qa2.x, B0); ffma2(acc[4][1], qa2.x, B1);
            ffma2(acc[4][2], qa2.x, B2); ffma2(acc[4][3], qa2.x, B3);
            ffma2(acc[5][0], qa2.y, B0); ffma2(acc[5][1], qa2.y, B1);
            ffma2(acc[5][2], qa2.y, B2); ffma2(acc[5][3], qa2.y, B3);
            ffma2(acc[6][0], qa3.x, B0); ffma2(acc[6][1], qa3.x, B1);
            ffma2(acc[6][2], qa3.x, B2); ffma2(acc[6][3], qa3.x, B3);
            ffma2(acc[7][0], qa3.y, B0); ffma2(acc[7][1], qa3.y, B1);
            ffma2(acc[7][2], qa3.y, B2); ffma2(acc[7][3], qa3.y, B3);
        }
        if (kt + 1 < IN_DIM / BK) {
            float* xn = xd + (buf ^ 1) * (BK * XDP);
            #pragma unroll
            for (int i = 0; i < 4; ++i) {
                float v = (i == 0) ? xs.x : (i == 1) ? xs.y : (i == 2) ? xs.z : xs.w;
                *(float2*)(xn + (xk + i) * XDP + 2 * xr) = make_float2(v, v);
            }
            CP_WAIT0;
        }
        __syncthreads();
    }

    // epilogue: +bias (packed), sumsq butterfly, store P rows + g_sq
    u64 bp0 = *(const u64*)(bias + nA);
    u64 bp1 = *(const u64*)(bias + nA + 2);
    u64 bp2 = *(const u64*)(bias + nB);
    u64 bp3 = *(const u64*)(bias + nB + 2);
    #pragma unroll
    for (int m = 0; m < 8; ++m) {
        fadd2(acc[m][0], bp0); fadd2(acc[m][1], bp1);
        fadd2(acc[m][2], bp2); fadd2(acc[m][3], bp3);
        u64 sp = 0ull;
        ffma2(sp, acc[m][0], acc[m][0]); ffma2(sp, acc[m][1], acc[m][1]);
        ffma2(sp, acc[m][2], acc[m][2]); ffma2(sp, acc[m][3], acc[m][3]);
        float lo, hi; unpack2(sp, lo, hi);
        float s = lo + hi;
        #pragma unroll
        for (int o = 16; o; o >>= 1) s += __shfl_xor_sync(0xffffffffu, s, o);
        int row = t0 + mb + m;
        u64* pr = (u64*)(g_P + (size_t)row * ED);
        pr[nA / 2]     = acc[m][0];
        pr[nA / 2 + 1] = acc[m][1];
        pr[nB / 2]     = acc[m][2];
        pr[nB / 2 + 1] = acc[m][3];
        if (lane == 0) g_sq[row] = s;
    }
}

// ---------------- K2: sims + top-2 + softmax (m-pair packed accs) ----------------
__global__ __launch_bounds__(256, 2)
void k2_kernel(float* __restrict__ out, int ntok) {
    extern __shared__ __align__(16) float sm2[];
    float* PsT = sm2;                      // [ED][PSTP] : P transposed [k][m]
    float* ct  = sm2 + ED * PSTP;          // [2][BK][NE] center tiles

    const int tid = threadIdx.x;
    const int w = tid >> 5, lane = tid & 31;
    const int t0 = blockIdx.x * TT;
    const int mb = (w >> 1) * 8;           // 8 rows per warp-pair
    const int nh = (w & 1) * 256;          // expert half
    const int nA = nh + lane * 4, nB = nh + 128 + lane * 4;

    uint32_t ct_u32 = (uint32_t)__cvta_generic_to_shared(ct);

    // ct prologue (kt=0) via cp.async
    const int cr = tid >> 7;               // 0..1
    const int cc = (tid & 127) * 4;        // 0..508
    #pragma unroll
    for (int j = 0; j < 8; ++j)
        cpa16(ct_u32 + (uint32_t)(((cr + 2 * j) * NE + cc) * 4),
              g_cnT + (size_t)(cr + 2 * j) * NE + cc);
    CP_COMMIT;

    // transpose P tile into PsT (overlaps with cp.async)
    const int pr = tid >> 3, pcq = (tid & 7) * 4;
    #pragma unroll
    for (int j = 0; j < 8; ++j) {
        int c = pcq + 32 * j;
        float4 v = *(const float4*)(g_P + (size_t)(t0 + pr) * ED + c);
        PsT[(c + 0) * PSTP + pr] = v.x;
        PsT[(c + 1) * PSTP + pr] = v.y;
        PsT[(c + 2) * PSTP + pr] = v.z;
        PsT[(c + 3) * PSTP + pr] = v.w;
    }
    CP_WAIT0;
    __syncthreads();

    u64 acc[4][8];
    #pragma unroll
    for (int p = 0; p < 4; ++p)
        #pragma unroll
        for (int j = 0; j < 8; ++j) acc[p][j] = 0ull;

    for (int kt = 0; kt < ED / BK; ++kt) {
        const int buf = kt & 1;
        const float* cb = ct + buf * (BK * NE);
        if (kt + 1 < ED / BK) {
            const float* csrc = g_cnT + (size_t)((kt + 1) * BK) * NE;
            uint32_t cdst = ct_u32 + (uint32_t)((buf ^ 1) * (BK * NE * 4));
            #pragma unroll
            for (int j = 0; j < 8; ++j)
                cpa16(cdst + (uint32_t)(((cr + 2 * j) * NE + cc) * 4),
                      csrc + (size_t)(cr + 2 * j) * NE + cc);
            CP_COMMIT;
        }
        #pragma unroll
        for (int k = 0; k < BK; ++k) {
            const int kk = kt * BK + k;
            const u64* ap = (const u64*)(PsT + kk * PSTP + mb);
            u64 a0 = ap[0], a1 = ap[1], a2 = ap[2], a3 = ap[3];
            float4 b0 = *(const float4*)(cb + k * NE + nA);
            float4 b1 = *(const float4*)(cb + k * NE + nB);
            u64 bb0 = pack2(b0.x, b0.x), bb1 = pack2(b0.y, b0.y);
            u64 bb2 = pack2(b0.z, b0.z), bb3 = pack2(b0.w, b0.w);
            u64 bb4 = pack2(b1.x, b1.x), bb5 = pack2(b1.y, b1.y);
            u64 bb6 = pack2(b1.z, b1.z), bb7 = pack2(b1.w, b1.w);
            ffma2(acc[0][0], a0, bb0); ffma2(acc[0][1], a0, bb1);
            ffma2(acc[0][2], a0, bb2); ffma2(acc[0][3], a0, bb3);
            ffma2(acc[0][4], a0, bb4); ffma2(acc[0][5], a0, bb5);
            ffma2(acc[0][6], a0, bb6); ffma2(acc[0][7], a0, bb7);
            ffma2(acc[1][0], a1, bb0); ffma2(acc[1][1], a1, bb1);
            ffma2(acc[1][2], a1, bb2); ffma2(acc[1][3], a1, bb3);
            ffma2(acc[1][4], a1, bb4); ffma2(acc[1][5], a1, bb5);
            ffma2(acc[1][6], a1, bb6); ffma2(acc[1][7], a1, bb7);
            ffma2(acc[2][0], a2, bb0); ffma2(acc[2][1], a2, bb1);
            ffma2(acc[2][2], a2, bb2); ffma2(acc[2][3], a2, bb3);
            ffma2(acc[2][4], a2, bb4); ffma2(acc[2][5], a2, bb5);
            ffma2(acc[2][6], a2, bb6); ffma2(acc[2][7], a2, bb7);
            ffma2(acc[3][0], a3, bb0); ffma2(acc[3][1], a3, bb1);
            ffma2(acc[3][2], a3, bb2); ffma2(acc[3][3], a3, bb3);
            ffma2(acc[3][4], a3, bb4); ffma2(acc[3][5], a3, bb5);
            ffma2(acc[3][6], a3, bb6); ffma2(acc[3][7], a3, bb7);
        }
        if (kt + 1 < ED / BK) { CP_WAIT0; }
        __syncthreads();
    }

    // per-thread -> per-warp top-2 over this warp's 256-expert half
    float v1[8], v2[8]; int i1[8], i2[8];
    #pragma unroll
    for (int r = 0; r < 8; ++r) { v1[r] = -INFINITY; v2[r] = -INFINITY; i1[r] = 0; i2[r] = 0; }
    #pragma unroll
    for (int p = 0; p < 4; ++p)
        #pragma unroll
        for (int j = 0; j < 8; ++j) {
            float lo, hi; unpack2(acc[p][j], lo, hi);
            int gi = (j < 4) ? (nA + j) : (nB + j - 4);
            upd(lo, gi, v1[2 * p],     i1[2 * p],     v2[2 * p],     i2[2 * p]);
            upd(hi, gi, v1[2 * p + 1], i1[2 * p + 1], v2[2 * p + 1], i2[2 * p + 1]);
        }
    #pragma unroll
    for (int r = 0; r < 8; ++r)
        #pragma unroll
        for (int o = 16; o; o >>= 1) {
            float o1 = __shfl_xor_sync(0xffffffffu, v1[r], o);
            int  oi1 = __shfl_xor_sync(0xffffffffu, i1[r], o);
            float o2 = __shfl_xor_sync(0xffffffffu, v2[r], o);
            int  oi2 = __shfl_xor_sync(0xffffffffu, i2[r], o);
            upd(o1, oi1, v1[r], i1[r], v2[r], i2[r]);
            upd(o2, oi2, v1[r], i1[r], v2[r], i2[r]);
        }

    // cross-half merge via smem (reuse ct buffer region, safe after last sync)
    float4* mg = (float4*)ct;              // [TT][2]
    if (lane == 0) {
        #pragma unroll
        for (int r = 0; r < 8; ++r)
            mg[(mb + r) * 2 + (w & 1)] =
                make_float4(v1[r], __int_as_float(i1[r]), v2[r], __int_as_float(i2[r]));
    }
    __syncthreads();

    if (tid < TT) {
        float4 A = mg[tid * 2 + 0];
        float4 B = mg[tid * 2 + 1];
        float V1 = A.x, V2 = A.z;
        int I1 = __float_as_int(A.y), I2 = __float_as_int(A.w);
        upd(B.x, __float_as_int(B.y), V1, I1, V2, I2);
        upd(B.z, __float_as_int(B.w), V1, I1, V2, I2);
        int token = t0 + tid;
        float inv = 1.f / fmaxf(sqrtf(g_sq[token]), 1e-12f);
        float s1 = V1 * inv, s2 = V2 * inv;
        float e2 = expf(s2 - s1);
        float den = 1.f + e2;
        out[2 * token]     = 1.f / den;
        out[2 * token + 1] = e2 / den;
        float* oi = out + 2 * (size_t)ntok;
        oi[2 * token]     = (float)I1;
        oi[2 * token + 1] = (float)I2;
    }
}

extern "C" void kernel_launch(void* const* d_in, const int* in_sizes, int n_in,
                              void* d_out, int out_size) {
    const float* x = (const float*)d_in[0];
    const float* W = (const float*)d_in[1];
    const float* b = (const float*)d_in[2];
    const float* c = (const float*)d_in[3];
    int ntok = in_sizes[0] / IN_DIM;   // 131072

    cnorm_kernel<<<NE, ED>>>(c);
    prep_wt_kernel<<<dim3(IN_DIM / 32, ED / 32), dim3(32, 8)>>>(W);

    int smem1 = (2 * BK * XDP + 2 * BK * ED) * (int)sizeof(float);   // 49664 B
    cudaFuncSetAttribute(k1_kernel, cudaFuncAttributeMaxDynamicSharedMemorySize, smem1);
    k1_kernel<<<ntok / 64, 256, smem1>>>(x, b);

    int smem2 = (ED * PSTP + 2 * BK * NE) * (int)sizeof(float);      // 100352 B
    cudaFuncSetAttribute(k2_kernel, cudaFuncAttributeMaxDynamicSharedMemorySize, smem2);
    k2_kernel<<<ntok / TT, 256, smem2>>>((float*)d_out, ntok);
}

// round 4
// speedup vs baseline: 2.1832x; 1.0485x over previous
#include <cuda_runtime.h>
#include <math.h>
#include <stdint.h>

#define IN_DIM 1024
#define ED 256
#define NE 512
#define NTOK_MAX 131072
#define TT 32
#define PSTP 34
#define XDP 132
#define BK1 32
#define BK2 16

typedef unsigned long long u64;

__device__ __align__(16) float g_WT[IN_DIM * ED];     // W transposed [k][n]
__device__ __align__(16) float g_cnT[ED * NE];        // normalized centers [k][e]
__device__ __align__(16) float g_P[(size_t)NTOK_MAX * ED];
__device__ float g_sq[NTOK_MAX];

static __device__ __forceinline__ u64 pack2(float lo, float hi) {
    u64 r; asm("mov.b64 %0, {%1, %2};" : "=l"(r) : "f"(lo), "f"(hi)); return r;
}
static __device__ __forceinline__ void unpack2(u64 v, float& lo, float& hi) {
    asm("mov.b64 {%0, %1}, %2;" : "=f"(lo), "=f"(hi) : "l"(v));
}
static __device__ __forceinline__ void ffma2(u64& d, u64 a, u64 b) {
    asm("fma.rn.f32x2 %0, %1, %2, %0;" : "+l"(d) : "l"(a), "l"(b));
}
static __device__ __forceinline__ void fadd2(u64& d, u64 a) {
    asm("add.rn.f32x2 %0, %0, %1;" : "+l"(d) : "l"(a));
}

// ---- bulk async copy + mbarrier helpers ----
static __device__ __forceinline__ void mbar_init(uint32_t mbar, uint32_t cnt) {
    asm volatile("mbarrier.init.shared.b64 [%0], %1;" :: "r"(mbar), "r"(cnt) : "memory");
}
static __device__ __forceinline__ void mbar_expect_tx(uint32_t mbar, uint32_t bytes) {
    asm volatile("mbarrier.arrive.expect_tx.shared.b64 _, [%0], %1;" :: "r"(mbar), "r"(bytes) : "memory");
}
static __device__ __forceinline__ void bulk_g2s(uint32_t dst, const float* src,
                                                uint32_t bytes, uint32_t mbar) {
    asm volatile("cp.async.bulk.shared::cta.global.mbarrier::complete_tx::bytes [%0], [%1], %2, [%3];"
                 :: "r"(dst), "l"(src), "r"(bytes), "r"(mbar) : "memory");
}
static __device__ __forceinline__ void mbar_wait(uint32_t mbar, uint32_t parity) {
    uint32_t done;
    asm volatile(
        "{\n\t.reg .pred p;\n\t"
        "mbarrier.try_wait.parity.acquire.cta.shared::cta.b64 p, [%1], %2;\n\t"
        "selp.b32 %0, 1, 0, p;\n\t}"
        : "=r"(done) : "r"(mbar), "r"(parity) : "memory");
    if (!done) {
        asm volatile(
            "{\n\t.reg .pred P1;\n\t"
            "WL_%=:\n\t"
            "mbarrier.try_wait.parity.acquire.cta.shared::cta.b64 P1, [%0], %1, 0x989680;\n\t"
            "@P1 bra.uni WD_%=;\n\t"
            "bra.uni WL_%=;\n\t"
            "WD_%=:\n\t}"
            :: "r"(mbar), "r"(parity) : "memory");
    }
}

static __device__ __forceinline__ void upd(float v, int i,
                                           float& v1, int& i1, float& v2, int& i2) {
    if (v > v1 || (v == v1 && i < i1)) { v2 = v1; i2 = i1; v1 = v; i1 = i; }
    else if (v > v2 || (v == v2 && i < i2)) { v2 = v; i2 = i; }
}

// ---------------- prep: normalize centers -> g_cnT [k][e] ----------------
__global__ void cnorm_kernel(const float* __restrict__ centers) {
    __shared__ float ws[8];
    int e = blockIdx.x, t = threadIdx.x;
    float v = centers[e * ED + t];
    float s = v * v;
    #pragma unroll
    for (int o = 16; o; o >>= 1) s += __shfl_xor_sync(0xffffffffu, s, o);
    if ((t & 31) == 0) ws[t >> 5] = s;
    __syncthreads();
    float tot = 0.f;
    #pragma unroll
    for (int i = 0; i < 8; ++i) tot += ws[i];
    float norm = fmaxf(sqrtf(tot), 1e-12f);
    g_cnT[t * NE + e] = v / norm;
}

// ---------------- prep: transpose W [n][k] -> g_WT [k][n] ----------------
__global__ void prep_wt_kernel(const float* __restrict__ W) {
    __shared__ float t[32][33];
    int bx = blockIdx.x * 32;
    int by = blockIdx.y * 32;
    int x = threadIdx.x, y = threadIdx.y;
    #pragma unroll
    for (int j = 0; j < 32; j += 8)
        t[y + j][x] = W[(size_t)(by + y + j) * IN_DIM + bx + x];
    __syncthreads();
    #pragma unroll
    for (int j = 0; j < 32; j += 8)
        g_WT[(size_t)(bx + y + j) * ED + by + x] = t[x][y + j];
}

// ---------------- K1: P = x @ W^T + b  (BK=32, bulk W tiles) ----------------
#define W1BYTES (BK1 * ED * 4)

__global__ __launch_bounds__(256, 2)
void k1_kernel(const float* __restrict__ x, const float* __restrict__ bias) {
    extern __shared__ __align__(16) float sm1[];
    float* xd = sm1;                       // [2][BK1][XDP]  duplicated x, k-major
    float* wS = sm1 + 2 * BK1 * XDP;       // [2][BK1][ED]   W tile, k-major
    __shared__ __align__(8) u64 mbars[2];

    const int tid = threadIdx.x;
    const int w = tid >> 5, lane = tid & 31;
    const int t0 = blockIdx.x * 64;
    const int mb = w * 8;
    const int nA = lane * 4, nB = 128 + lane * 4;

    const int xr = tid >> 2, xk = (tid & 3) * 8;
    const float* xp = x + (size_t)(t0 + xr) * IN_DIM + xk;

    uint32_t wS_u32 = (uint32_t)__cvta_generic_to_shared(wS);
    uint32_t mb0 = (uint32_t)__cvta_generic_to_shared(&mbars[0]);
    uint32_t mb1 = mb0 + 8;
    int ph0 = 0, ph1 = 0;

    u64 acc[8][4];
    #pragma unroll
    for (int m = 0; m < 8; ++m)
        #pragma unroll
        for (int p = 0; p < 4; ++p) acc[m][p] = 0ull;

    if (tid == 0) { mbar_init(mb0, 1); mbar_init(mb1, 1); }
    __syncthreads();

    // prologue: bulk W tile 0, stage x tile 0
    if (tid == 0) { mbar_expect_tx(mb0, W1BYTES); bulk_g2s(wS_u32, g_WT, W1BYTES, mb0); }
    float4 xs0 = *(const float4*)xp;
    float4 xs1 = *(const float4*)(xp + 4);
    {
        float v[8] = {xs0.x, xs0.y, xs0.z, xs0.w, xs1.x, xs1.y, xs1.z, xs1.w};
        #pragma unroll
        for (int i = 0; i < 8; ++i)
            *(float2*)(xd + (xk + i) * XDP + 2 * xr) = make_float2(v[i], v[i]);
    }
    mbar_wait(mb0, ph0); ph0 ^= 1;
    __syncthreads();

    const int NT = IN_DIM / BK1;
    for (int kt = 0; kt < NT; ++kt) {
        const int buf = kt & 1;
        const float* xb = xd + buf * (BK1 * XDP);
        const float* wb = wS + buf * (BK1 * ED);
        if (kt + 1 < NT) {
            if (tid == 0) {
                uint32_t m = buf ? mb0 : mb1;
                mbar_expect_tx(m, W1BYTES);
                bulk_g2s(wS_u32 + (uint32_t)((buf ^ 1) * W1BYTES),
                         g_WT + (size_t)(kt + 1) * BK1 * ED, W1BYTES, m);
            }
            xs0 = *(const float4*)(xp + (kt + 1) * BK1);
            xs1 = *(const float4*)(xp + (kt + 1) * BK1 + 4);
        }
        #pragma unroll
        for (int k = 0; k < BK1; ++k) {
            ulonglong2 qa0 = *(const ulonglong2*)(xb + k * XDP + 2 * mb + 0);
            ulonglong2 qa1 = *(const ulonglong2*)(xb + k * XDP + 2 * mb + 4);
            ulonglong2 qa2 = *(const ulonglong2*)(xb + k * XDP + 2 * mb + 8);
            ulonglong2 qa3 = *(const ulonglong2*)(xb + k * XDP + 2 * mb + 12);
            ulonglong2 qb0 = *(const ulonglong2*)(wb + k * ED + nA);
            ulonglong2 qb1 = *(const ulonglong2*)(wb + k * ED + nB);
            u64 B0 = qb0.x, B1 = qb0.y, B2 = qb1.x, B3 = qb1.y;
            ffma2(acc[0][0], qa0.x, B0); ffma2(acc[0][1], qa0.x, B1);
            ffma2(acc[0][2], qa0.x, B2); ffma2(acc[0][3], qa0.x, B3);
            ffma2(acc[1][0], qa0.y, B0); ffma2(acc[1][1], qa0.y, B1);
            ffma2(acc[1][2], qa0.y, B2); ffma2(acc[1][3], qa0.y, B3);
            ffma2(acc[2][0], qa1.x, B0); ffma2(acc[2][1], qa1.x, B1);
            ffma2(acc[2][2], qa1.x, B2); ffma2(acc[2][3], qa1.x, B3);
            ffma2(acc[3][0], qa1.y, B0); ffma2(acc[3][1], qa1.y, B1);
            ffma2(acc[3][2], qa1.y, B2); ffma2(acc[3][3], qa1.y, B3);
            ffma2(acc[4][0], qa2.x, B0); ffma2(acc[4][1], qa2.x, B1);
            ffma2(acc[4][2], qa2.x, B2); ffma2(acc[4][3], qa2.x, B3);
            ffma2(acc[5][0], qa2.y, B0); ffma2(acc[5][1], qa2.y, B1);
            ffma2(acc[5][2], qa2.y, B2); ffma2(acc[5][3], qa2.y, B3);
            ffma2(acc[6][0], qa3.x, B0); ffma2(acc[6][1], qa3.x, B1);
            ffma2(acc[6][2], qa3.x, B2); ffma2(acc[6][3], qa3.x, B3);
            ffma2(acc[7][0], qa3.y, B0); ffma2(acc[7][1], qa3.y, B1);
            ffma2(acc[7][2], qa3.y, B2); ffma2(acc[7][3], qa3.y, B3);
        }
        if (kt + 1 < NT) {
            float* xn = xd + (buf ^ 1) * (BK1 * XDP);
            float v[8] = {xs0.x, xs0.y, xs0.z, xs0.w, xs1.x, xs1.y, xs1.z, xs1.w};
            #pragma unroll
            for (int i = 0; i < 8; ++i)
                *(float2*)(xn + (xk + i) * XDP + 2 * xr) = make_float2(v[i], v[i]);
            if (buf) { mbar_wait(mb0, ph0); ph0 ^= 1; }
            else     { mbar_wait(mb1, ph1); ph1 ^= 1; }
        }
        __syncthreads();
    }

    // epilogue: +bias (packed), sumsq butterfly, store P rows + g_sq
    u64 bp0 = *(const u64*)(bias + nA);
    u64 bp1 = *(const u64*)(bias + nA + 2);
    u64 bp2 = *(const u64*)(bias + nB);
    u64 bp3 = *(const u64*)(bias + nB + 2);
    #pragma unroll
    for (int m = 0; m < 8; ++m) {
        fadd2(acc[m][0], bp0); fadd2(acc[m][1], bp1);
        fadd2(acc[m][2], bp2); fadd2(acc[m][3], bp3);
        u64 sp = 0ull;
        ffma2(sp, acc[m][0], acc[m][0]); ffma2(sp, acc[m][1], acc[m][1]);
        ffma2(sp, acc[m][2], acc[m][2]); ffma2(sp, acc[m][3], acc[m][3]);
        float lo, hi; unpack2(sp, lo, hi);
        float s = lo + hi;
        #pragma unroll
        for (int o = 16; o; o >>= 1) s += __shfl_xor_sync(0xffffffffu, s, o);
        int row = t0 + mb + m;
        u64* pr = (u64*)(g_P + (size_t)row * ED);
        pr[nA / 2]     = acc[m][0];
        pr[nA / 2 + 1] = acc[m][1];
        pr[nB / 2]     = acc[m][2];
        pr[nB / 2 + 1] = acc[m][3];
        if (lane == 0) g_sq[row] = s;
    }
}

// ---------------- K2: sims + top-2 + softmax (bulk center tiles) ----------------
#define C2BYTES (BK2 * NE * 4)

__global__ __launch_bounds__(256, 2)
void k2_kernel(float* __restrict__ out, int ntok) {
    extern __shared__ __align__(16) float sm2[];
    float* PsT = sm2;                      // [ED][PSTP] : P transposed [k][m]
    float* ct  = sm2 + ED * PSTP;          // [2][BK2][NE] center tiles
    __shared__ __align__(8) u64 mbars[2];

    const int tid = threadIdx.x;
    const int w = tid >> 5, lane = tid & 31;
    const int t0 = blockIdx.x * TT;
    const int mb = (w >> 1) * 8;
    const int nh = (w & 1) * 256;
    const int nA = nh + lane * 4, nB = nh + 128 + lane * 4;

    uint32_t ct_u32 = (uint32_t)__cvta_generic_to_shared(ct);
    uint32_t mb0 = (uint32_t)__cvta_generic_to_shared(&mbars[0]);
    uint32_t mb1 = mb0 + 8;
    int ph0 = 0, ph1 = 0;

    if (tid == 0) { mbar_init(mb0, 1); mbar_init(mb1, 1); }
    __syncthreads();
    if (tid == 0) { mbar_expect_tx(mb0, C2BYTES); bulk_g2s(ct_u32, g_cnT, C2BYTES, mb0); }

    // transpose P tile into PsT (overlaps with bulk copy)
    const int pr = tid >> 3, pcq = (tid & 7) * 4;
    #pragma unroll
    for (int j = 0; j < 8; ++j) {
        int c = pcq + 32 * j;
        float4 v = *(const float4*)(g_P + (size_t)(t0 + pr) * ED + c);
        PsT[(c + 0) * PSTP + pr] = v.x;
        PsT[(c + 1) * PSTP + pr] = v.y;
        PsT[(c + 2) * PSTP + pr] = v.z;
        PsT[(c + 3) * PSTP + pr] = v.w;
    }
    mbar_wait(mb0, ph0); ph0 ^= 1;
    __syncthreads();

    u64 acc[4][8];
    #pragma unroll
    for (int p = 0; p < 4; ++p)
        #pragma unroll
        for (int j = 0; j < 8; ++j) acc[p][j] = 0ull;

    const int NT = ED / BK2;
    for (int kt = 0; kt < NT; ++kt) {
        const int buf = kt & 1;
        const float* cb = ct + buf * (BK2 * NE);
        if (kt + 1 < NT && tid == 0) {
            uint32_t m = buf ? mb0 : mb1;
            mbar_expect_tx(m, C2BYTES);
            bulk_g2s(ct_u32 + (uint32_t)((buf ^ 1) * C2BYTES),
                     g_cnT + (size_t)(kt + 1) * BK2 * NE, C2BYTES, m);
        }
        #pragma unroll
        for (int k = 0; k < BK2; ++k) {
            const int kk = kt * BK2 + k;
            const u64* ap = (const u64*)(PsT + kk * PSTP + mb);
            u64 a0 = ap[0], a1 = ap[1], a2 = ap[2], a3 = ap[3];
            float4 b0 = *(const float4*)(cb + k * NE + nA);
            float4 b1 = *(const float4*)(cb + k * NE + nB);
            u64 bb0 = pack2(b0.x, b0.x), bb1 = pack2(b0.y, b0.y);
            u64 bb2 = pack2(b0.z, b0.z), bb3 = pack2(b0.w, b0.w);
            u64 bb4 = pack2(b1.x, b1.x), bb5 = pack2(b1.y, b1.y);
            u64 bb6 = pack2(b1.z, b1.z), bb7 = pack2(b1.w, b1.w);
            ffma2(acc[0][0], a0, bb0); ffma2(acc[0][1], a0, bb1);
            ffma2(acc[0][2], a0, bb2); ffma2(acc[0][3], a0, bb3);
            ffma2(acc[0][4], a0, bb4); ffma2(acc[0][5], a0, bb5);
            ffma2(acc[0][6], a0, bb6); ffma2(acc[0][7], a0, bb7);
            ffma2(acc[1][0], a1, bb0); ffma2(acc[1][1], a1, bb1);
            ffma2(acc[1][2], a1, bb2); ffma2(acc[1][3], a1, bb3);
            ffma2(acc[1][4], a1, bb4); ffma2(acc[1][5], a1, bb5);
            ffma2(acc[1][6], a1, bb6); ffma2(acc[1][7], a1, bb7);
            ffma2(acc[2][0], a2, bb0); ffma2(acc[2][1], a2, bb1);
            ffma2(acc[2][2], a2, bb2); ffma2(acc[2][3], a2, bb3);
            ffma2(acc[2][4], a2, bb4); ffma2(acc[2][5], a2, bb5);
            ffma2(acc[2][6], a2, bb6); ffma2(acc[2][7], a2, bb7);
            ffma2(acc[3][0], a3, bb0); ffma2(acc[3][1], a3, bb1);
            ffma2(acc[3][2], a3, bb2); ffma2(acc[3][3], a3, bb3);
            ffma2(acc[3][4], a3, bb4); ffma2(acc[3][5], a3, bb5);
            ffma2(acc[3][6], a3, bb6); ffma2(acc[3][7], a3, bb7);
        }
        if (kt + 1 < NT) {
            if (buf) { mbar_wait(mb0, ph0); ph0 ^= 1; }
            else     { mbar_wait(mb1, ph1); ph1 ^= 1; }
        }
        __syncthreads();
    }

    // per-thread -> per-warp top-2 over this warp's 256-expert half
    float v1[8], v2[8]; int i1[8], i2[8];
    #pragma unroll
    for (int r = 0; r < 8; ++r) { v1[r] = -INFINITY; v2[r] = -INFINITY; i1[r] = 0; i2[r] = 0; }
    #pragma unroll
    for (int p = 0; p < 4; ++p)
        #pragma unroll
        for (int j = 0; j < 8; ++j) {
            float lo, hi; unpack2(acc[p][j], lo, hi);
            int gi = (j < 4) ? (nA + j) : (nB + j - 4);
            upd(lo, gi, v1[2 * p],     i1[2 * p],     v2[2 * p],     i2[2 * p]);
            upd(hi, gi, v1[2 * p + 1], i1[2 * p + 1], v2[2 * p + 1], i2[2 * p + 1]);
        }
    #pragma unroll
    for (int r = 0; r < 8; ++r)
        #pragma unroll
        for (int o = 16; o; o >>= 1) {
            float o1 = __shfl_xor_sync(0xffffffffu, v1[r], o);
            int  oi1 = __shfl_xor_sync(0xffffffffu, i1[r], o);
            float o2 = __shfl_xor_sync(0xffffffffu, v2[r], o);
            int  oi2 = __shfl_xor_sync(0xffffffffu, i2[r], o);
            upd(o1, oi1, v1[r], i1[r], v2[r], i2[r]);
            upd(o2, oi2, v1[r], i1[r], v2[r], i2[r]);
        }

    // cross-half merge via smem (reuse ct region, safe after last sync)
    float4* mg = (float4*)ct;              // [TT][2]
    if (lane == 0) {
        #pragma unroll
        for (int r = 0; r < 8; ++r)
            mg[(mb + r) * 2 + (w & 1)] =
                make_float4(v1[r], __int_as_float(i1[r]), v2[r], __int_as_float(i2[r]));
    }
    __syncthreads();

    if (tid < TT) {
        float4 A = mg[tid * 2 + 0];
        float4 B = mg[tid * 2 + 1];
        float V1 = A.x, V2 = A.z;
        int I1 = __float_as_int(A.y), I2 = __float_as_int(A.w);
        upd(B.x, __float_as_int(B.y), V1, I1, V2, I2);
        upd(B.z, __float_as_int(B.w), V1, I1, V2, I2);
        int token = t0 + tid;
        float inv = 1.f / fmaxf(sqrtf(g_sq[token]), 1e-12f);
        float s1 = V1 * inv, s2 = V2 * inv;
        float e2 = expf(s2 - s1);
        float den = 1.f + e2;
        out[2 * token]     = 1.f / den;
        out[2 * token + 1] = e2 / den;
        float* oi = out + 2 * (size_t)ntok;
        oi[2 * token]     = (float)I1;
        oi[2 * token + 1] = (float)I2;
    }
}

extern "C" void kernel_launch(void* const* d_in, const int* in_sizes, int n_in,
                              void* d_out, int out_size) {
    const float* x = (const float*)d_in[0];
    const float* W = (const float*)d_in[1];
    const float* b = (const float*)d_in[2];
    const float* c = (const float*)d_in[3];
    int ntok = in_sizes[0] / IN_DIM;   // 131072

    cnorm_kernel<<<NE, ED>>>(c);
    prep_wt_kernel<<<dim3(IN_DIM / 32, ED / 32), dim3(32, 8)>>>(W);

    int smem1 = (2 * BK1 * XDP + 2 * BK1 * ED) * (int)sizeof(float);   // 99328 B
    cudaFuncSetAttribute(k1_kernel, cudaFuncAttributeMaxDynamicSharedMemorySize, smem1);
    k1_kernel<<<ntok / 64, 256, smem1>>>(x, b);

    int smem2 = (ED * PSTP + 2 * BK2 * NE) * (int)sizeof(float);       // 100352 B
    cudaFuncSetAttribute(k2_kernel, cudaFuncAttributeMaxDynamicSharedMemorySize, smem2);
    k2_kernel<<<ntok / TT, 256, smem2>>>((float*)d_out, ntok);
}